// round 7
// baseline (speedup 1.0000x reference)
#include <cuda_runtime.h>
#include <cuda_fp16.h>
#include <math.h>
#include <stdint.h>

// Problem constants
#define B_   4
#define L_   2048
#define DIM_ 1024
#define DFF_ 4096
#define NTOK (B_ * L_)            // 8192 rows
#define CS   64                    // conv chunk size
#define NC   (L_ / CS)             // 32 chunks

// Offload split: GEMM1 cols [0,3840) HMMA + [3840,4096) FFMA
//                GEMM2 cols [0,960)  HMMA + [960,1024)  FFMA
#define G1_HN 3840
#define G2_HN 960

// -------- scratch (static __device__ — no allocations allowed) --------
__device__ float   g_y  [(size_t)NTOK * DIM_];
__device__ __half  g_h2h[(size_t)NTOK * DIM_];   // LN2 out, fp16
__device__ __half  g_act[(size_t)NTOK * DFF_];   // SiLU out, fp16
__device__ __half  g_w1h[(size_t)DFF_ * DIM_];   // w1^T fp16 [N=4096,K=1024]
__device__ __half  g_w2h[(size_t)DIM_ * DFF_];   // w2^T fp16 [N=1024,K=4096]
__device__ float2  g_stat[NTOK];                 // LN1 (mu, rstd) per row
__device__ float2  g_carry[B_ * NC * DIM_];
__device__ float2  g_zin  [B_ * NC * DIM_];
__device__ float2  g_p    [DIM_];
__device__ float2  g_pinit[DIM_];
__device__ float2  g_p64  [DIM_];

// ================= helpers =================
__device__ __forceinline__ uint32_t smem_u32(const void* p) {
    return (uint32_t)__cvta_generic_to_shared(p);
}
__device__ __forceinline__ void cp_async16(uint32_t saddr, const void* gptr) {
    asm volatile("cp.async.cg.shared.global [%0], [%1], 16;" :: "r"(saddr), "l"(gptr));
}
#define CP_COMMIT()  asm volatile("cp.async.commit_group;" ::: "memory")
#define CP_WAIT(n)   asm volatile("cp.async.wait_group %0;" :: "n"(n) : "memory")
#define LDSM_X4(r0, r1, r2, r3, addr) \
    asm volatile("ldmatrix.sync.aligned.m8n8.x4.shared.b16 {%0,%1,%2,%3}, [%4];" \
                 : "=r"(r0), "=r"(r1), "=r"(r2), "=r"(r3) : "r"(addr))

// ================= phazor precompute =================
__global__ void phazor_prep(const float* __restrict__ phazor,
                            const float* __restrict__ phazor_init) {
    int d = blockIdx.x * blockDim.x + threadIdx.x;
    if (d >= DIM_) return;
    float pr = phazor[2 * d], pim = phazor[2 * d + 1];
    float pa = sqrtf(pr * pr + pim * pim);
    float s = expf(-pa) / pa;
    float2 p = make_float2(pr * s, pim * s);
    g_p[d] = p;
    g_pinit[d] = make_float2(phazor_init[2 * d], phazor_init[2 * d + 1]);
    float2 q = p;
    #pragma unroll
    for (int i = 0; i < 6; i++) {
        float nr = q.x * q.x - q.y * q.y;
        q.y = 2.f * q.x * q.y;
        q.x = nr;
    }
    g_p64[d] = q;
}

// ========== LN1 stats: warp per row ==========
__global__ void ln_stats(const float* __restrict__ x) {
    int row = blockIdx.x * 8 + (threadIdx.x >> 5);
    int lane = threadIdx.x & 31;
    const float4* xr = (const float4*)(x + (size_t)row * DIM_);
    float s = 0.f, ss = 0.f;
    #pragma unroll
    for (int i = 0; i < 8; i++) {
        float4 v = xr[lane + 32 * i];
        s  += v.x + v.y + v.z + v.w;
        ss += v.x * v.x + v.y * v.y + v.z * v.z + v.w * v.w;
    }
    #pragma unroll
    for (int o = 16; o > 0; o >>= 1) {
        s  += __shfl_xor_sync(0xffffffffu, s, o);
        ss += __shfl_xor_sync(0xffffffffu, ss, o);
    }
    if (lane == 0) {
        float mu = s * (1.f / DIM_);
        float var = ss * (1.f / DIM_) - mu * mu;
        g_stat[row] = make_float2(mu, rsqrtf(var + 1e-5f));
    }
}

// ========== LN2 (warp per row, fp32 in -> fp16 out) ==========
__global__ void ln2_kernel(const float* __restrict__ x, const float* __restrict__ g,
                           const float* __restrict__ bb, __half* __restrict__ out16) {
    int row = blockIdx.x * 8 + (threadIdx.x >> 5);
    int lane = threadIdx.x & 31;
    const float4* xr = (const float4*)(x + (size_t)row * DIM_);
    float4 vv[8];
    float s = 0.f, ss = 0.f;
    #pragma unroll
    for (int i = 0; i < 8; i++) {
        float4 v = xr[lane + 32 * i];
        vv[i] = v;
        s  += v.x + v.y + v.z + v.w;
        ss += v.x * v.x + v.y * v.y + v.z * v.z + v.w * v.w;
    }
    #pragma unroll
    for (int o = 16; o > 0; o >>= 1) {
        s  += __shfl_xor_sync(0xffffffffu, s, o);
        ss += __shfl_xor_sync(0xffffffffu, ss, o);
    }
    float mu  = s * (1.f / DIM_);
    float var = ss * (1.f / DIM_) - mu * mu;
    float inv = rsqrtf(var + 1e-5f);
    #pragma unroll
    for (int i = 0; i < 8; i++) {
        float4 gv = ((const float4*)g)[lane + 32 * i];
        float4 bv = ((const float4*)bb)[lane + 32 * i];
        float4 v = vv[i];
        __half2 h0 = __floats2half2_rn((v.x - mu) * inv * gv.x + bv.x,
                                       (v.y - mu) * inv * gv.y + bv.y);
        __half2 h1 = __floats2half2_rn((v.z - mu) * inv * gv.z + bv.z,
                                       (v.w - mu) * inv * gv.w + bv.w);
        uint2 pk = make_uint2(*(uint32_t*)&h0, *(uint32_t*)&h1);
        *(uint2*)(out16 + (size_t)row * DIM_ + (lane + 32 * i) * 4) = pk;
    }
}

// ================= spiral conv: 3-phase chunked scan =================
__global__ void conv_phase1(const float* __restrict__ x, const float* __restrict__ lng,
                            const float* __restrict__ lnb) {
    int b = blockIdx.x >> 5, c = blockIdx.x & 31, d = threadIdx.x;
    float2 p = g_p[d];
    float gd = lng[d], bd = lnb[d];
    float zr = 0.f, zi = 0.f;
    int row0 = b * L_ + c * CS;
    const float* xp = x + (size_t)row0 * DIM_ + d;
    #pragma unroll 4
    for (int j = 0; j < CS; j++) {
        float2 st = g_stat[row0 + j];
        float hv = (xp[(size_t)j * DIM_] - st.x) * st.y * gd + bd;
        float nr = p.x * zr - p.y * zi + hv;
        zi = p.x * zi + p.y * zr;
        zr = nr;
    }
    g_carry[(b * NC + c) * DIM_ + d] = make_float2(zr, zi);
}

__global__ void conv_phase2() {
    int b = blockIdx.x;
    int d = blockIdx.y * 256 + threadIdx.x;
    float2 pc = g_p64[d];
    float2 cv[NC];
    #pragma unroll
    for (int c = 0; c < NC; c++) cv[c] = g_carry[(b * NC + c) * DIM_ + d];
    float zr = 0.f, zi = 0.f;
    #pragma unroll
    for (int c = 0; c < NC; c++) {
        g_zin[(b * NC + c) * DIM_ + d] = make_float2(zr, zi);
        float nr = pc.x * zr - pc.y * zi + cv[c].x;
        zi = pc.x * zi + pc.y * zr + cv[c].y;
        zr = nr;
    }
}

__global__ void conv_phase3(const float* __restrict__ x, const float* __restrict__ lng,
                            const float* __restrict__ lnb,
                            const float* __restrict__ lre, const float* __restrict__ lim,
                            float* __restrict__ y) {
    int b = blockIdx.x >> 5, c = blockIdx.x & 31, d = threadIdx.x;
    float2 p  = g_p[d];
    float2 pi = g_pinit[d];
    float2 pc = g_p64[d];
    float2 z  = g_zin[(b * NC + c) * DIM_ + d];
    float gd = lng[d], bd = lnb[d];
    float twr = 1.f, twi = 0.f;
    for (int i = 0; i < c; i++) {
        float nr = twr * pc.x - twi * pc.y;
        twi = twr * pc.y + twi * pc.x;
        twr = nr;
    }
    float pwr = twr * p.x - twi * p.y;
    float pwi = twr * p.y + twi * p.x;
    float lr = lre[b * DIM_ + d], li = lim[b * DIM_ + d];
    int row0 = b * L_ + c * CS;
    size_t base = (size_t)row0 * DIM_ + d;
    #pragma unroll 4
    for (int j = 0; j < CS; j++) {
        float xv = x[base + (size_t)j * DIM_];
        float2 st = g_stat[row0 + j];
        float hv = (xv - st.x) * st.y * gd + bd;
        float nr = p.x * z.x - p.y * z.y + hv;
        z.y = p.x * z.y + p.y * z.x;
        z.x = nr;
        float val = pi.x * z.x - pi.y * z.y + lr * pwr - li * pwi;
        y[base + (size_t)j * DIM_] = val + xv;
        float npr = pwr * p.x - pwi * p.y;
        pwi = pwr * p.y + pwi * p.x;
        pwr = npr;
    }
}

// ======== weight transpose + cast ([K,N] fp32 -> [N,K] fp16) ========
__global__ void transpose_h(const float* __restrict__ in, __half* __restrict__ out,
                            int R, int Ccols) {
    __shared__ float t[32][33];
    int bx = blockIdx.x * 32, by = blockIdx.y * 32;
    int tx = threadIdx.x, ty = threadIdx.y;
    #pragma unroll
    for (int j = 0; j < 32; j += 8)
        t[ty + j][tx] = in[(size_t)(by + ty + j) * Ccols + bx + tx];
    __syncthreads();
    #pragma unroll
    for (int j = 0; j < 32; j += 8)
        out[(size_t)(bx + ty + j) * R + by + tx] = __float2half(t[tx][ty + j]);
}

// ======= fp16 tensor-core GEMM (mma.sync m16n8k16 + ldmatrix) =======
#define TBK 32
#define ROW_H 72                         // padded stride in halves (144B)

template <int EPI, int CTN>
__global__ __launch_bounds__(256, (CTN <= 128) ? 2 : 1) void hgemm(
    const __half* __restrict__ A, const __half* __restrict__ Bt,
    const float* __restrict__ bias, const float* __restrict__ res,
    __half* __restrict__ Ch, float* __restrict__ Cf, int M, int N, int K) {
    constexpr int WNW = CTN / 4;         // warp n-width
    constexpr int NT  = WNW / 8;         // n-subtiles
    constexpr int NP  = NT / 2;          // ldmatrix x4 B loads
    constexpr int BCH = CTN / 64;        // B 16B-chunks per thread
    constexpr int A_H = 128 * ROW_H;
    constexpr int STG = (128 + CTN) * ROW_H;

    extern __shared__ __half sm[];
    int tid = threadIdx.x, wid = tid >> 5, lane = tid & 31;
    int g = lane >> 2, l4 = lane & 3;
    int wm = (wid & 1) * 64;
    int wn = (wid >> 1) * WNW;
    int bm = blockIdx.y * 128, bn = blockIdx.x * CTN;
    const int NK = K / TBK;

    int mat = lane >> 3, rr = lane & 7;
    uint32_t aoff[4], boff[NP];
    #pragma unroll
    for (int mt = 0; mt < 4; mt++)
        aoff[mt] = (uint32_t)((wm + mt * 16 + (mat & 1) * 8 + rr) * 144 + (mat >> 1) * 16);
    #pragma unroll
    for (int np = 0; np < NP; np++)
        boff[np] = (uint32_t)((wn + np * 16 + (mat >> 1) * 8 + rr) * 144 + (mat & 1) * 16);

    auto load_stage = [&](int s, int k0) {
        uint32_t base = smem_u32(sm + (size_t)s * STG);
        #pragma unroll
        for (int i = 0; i < 2; i++) {
            int c = tid + i * 256;
            int row = c >> 2, kc = c & 3;
            cp_async16(base + row * 144 + kc * 16,
                       A + (size_t)(bm + row) * K + k0 + kc * 8);
        }
        uint32_t bb = base + A_H * 2;
        #pragma unroll
        for (int i = 0; i < BCH; i++) {
            int c = tid + i * 256;
            int row = c >> 2, kc = c & 3;
            cp_async16(bb + row * 144 + kc * 16,
                       Bt + (size_t)(bn + row) * K + k0 + kc * 8);
        }
    };

    float acc[4][NT][4];
    #pragma unroll
    for (int i = 0; i < 4; i++)
        #pragma unroll
        for (int j = 0; j < NT; j++)
            #pragma unroll
            for (int r = 0; r < 4; r++) acc[i][j][r] = 0.f;

    load_stage(0, 0);       CP_COMMIT();
    load_stage(1, TBK);     CP_COMMIT();

    for (int kt = 0; kt < NK; kt++) {
        if (kt + 1 < NK) CP_WAIT(1); else CP_WAIT(0);
        __syncthreads();
        if (kt + 2 < NK) load_stage((kt + 2) % 3, (kt + 2) * TBK);
        CP_COMMIT();
        uint32_t sa = smem_u32(sm + (size_t)(kt % 3) * STG);
        uint32_t sb = sa + A_H * 2;
        #pragma unroll
        for (int ks = 0; ks < TBK; ks += 16) {
            uint32_t af[4][4], bf[NT][2];
            #pragma unroll
            for (int mt = 0; mt < 4; mt++)
                LDSM_X4(af[mt][0], af[mt][1], af[mt][2], af[mt][3],
                        sa + aoff[mt] + ks * 2);
            #pragma unroll
            for (int np = 0; np < NP; np++)
                LDSM_X4(bf[2 * np][0], bf[2 * np][1], bf[2 * np + 1][0], bf[2 * np + 1][1],
                        sb + boff[np] + ks * 2);
            #pragma unroll
            for (int mt = 0; mt < 4; mt++)
                #pragma unroll
                for (int nt = 0; nt < NT; nt++) {
                    asm volatile(
                        "mma.sync.aligned.m16n8k16.row.col.f32.f16.f16.f32 "
                        "{%0,%1,%2,%3}, {%4,%5,%6,%7}, {%8,%9}, {%0,%1,%2,%3};"
                        : "+f"(acc[mt][nt][0]), "+f"(acc[mt][nt][1]),
                          "+f"(acc[mt][nt][2]), "+f"(acc[mt][nt][3])
                        : "r"(af[mt][0]), "r"(af[mt][1]), "r"(af[mt][2]), "r"(af[mt][3]),
                          "r"(bf[nt][0]), "r"(bf[nt][1]));
                }
        }
    }

    #pragma unroll
    for (int mt = 0; mt < 4; mt++) {
        int r0 = bm + wm + mt * 16 + g;
        #pragma unroll
        for (int nt = 0; nt < NT; nt++) {
            int col = bn + wn + nt * 8 + 2 * l4;
            float bv0 = bias[col], bv1 = bias[col + 1];
            #pragma unroll
            for (int h = 0; h < 2; h++) {
                int row = r0 + h * 8;
                size_t off = (size_t)row * N + col;
                float v0 = acc[mt][nt][2 * h + 0] + bv0;
                float v1 = acc[mt][nt][2 * h + 1] + bv1;
                if (EPI == 0) {
                    v0 = v0 / (1.f + expf(-v0));
                    v1 = v1 / (1.f + expf(-v1));
                    __half2 hv = __floats2half2_rn(v0, v1);
                    *(__half2*)&Ch[off] = hv;
                } else {
                    v0 += res[off];
                    v1 += res[off + 1];
                    *(float2*)&Cf[off] = make_float2(v0, v1);
                }
            }
        }
    }
}

// ======= fp32 SIMT offload GEMMs (run concurrent with hgemm on FMA pipe) ======
// GEMM1 offload: C[:,n0:n0+256) = silu(h2h @ w1 + b1), 128x128 tile
__global__ __launch_bounds__(256) void sgemm_silu(
    const __half* __restrict__ A, const float* __restrict__ W,
    const float* __restrict__ bias, __half* __restrict__ C,
    int M, int N, int K, int n0) {
    __shared__ float As[8][128];
    __shared__ float Bs[8][128];
    int bm = blockIdx.y * 128, bn = n0 + blockIdx.x * 128;
    int tid = threadIdx.x;
    int arow = tid >> 1, acol = (tid & 1) * 4;
    int brow = tid >> 5, bcol = (tid & 31) * 4;
    int tm0 = (tid >> 4) * 8, tn0 = (tid & 15) * 8;
    float acc[8][8];
    #pragma unroll
    for (int i = 0; i < 8; i++)
        #pragma unroll
        for (int j = 0; j < 8; j++) acc[i][j] = 0.f;

    for (int k0 = 0; k0 < K; k0 += 8) {
        uint2 araw = *(const uint2*)(A + (size_t)(bm + arow) * K + k0 + acol);
        __half2 a0 = *(__half2*)&araw.x, a1 = *(__half2*)&araw.y;
        As[acol + 0][arow] = __low2float(a0);
        As[acol + 1][arow] = __high2float(a0);
        As[acol + 2][arow] = __low2float(a1);
        As[acol + 3][arow] = __high2float(a1);
        *(float4*)&Bs[brow][bcol] =
            *(const float4*)&W[(size_t)(k0 + brow) * N + bn + bcol];
        __syncthreads();
        #pragma unroll
        for (int k = 0; k < 8; k++) {
            float ra[8], rb[8];
            *(float4*)(ra)     = *(float4*)&As[k][tm0];
            *(float4*)(ra + 4) = *(float4*)&As[k][tm0 + 4];
            *(float4*)(rb)     = *(float4*)&Bs[k][tn0];
            *(float4*)(rb + 4) = *(float4*)&Bs[k][tn0 + 4];
            #pragma unroll
            for (int i = 0; i < 8; i++)
                #pragma unroll
                for (int j = 0; j < 8; j++) acc[i][j] += ra[i] * rb[j];
        }
        __syncthreads();
    }
    #pragma unroll
    for (int i = 0; i < 8; i++) {
        size_t rowoff = (size_t)(bm + tm0 + i) * N + bn + tn0;
        __half hb[8];
        #pragma unroll
        for (int j = 0; j < 8; j++) {
            float v = acc[i][j] + bias[bn + tn0 + j];
            v = v / (1.f + expf(-v));
            hb[j] = __float2half(v);
        }
        *(uint4*)&C[rowoff] = *(uint4*)hb;
    }
}

// GEMM2 offload: out[:,n0:n0+64) = act @ w2 + b2 + y, 64x64 tile
__global__ __launch_bounds__(256) void sgemm_res(
    const __half* __restrict__ A, const float* __restrict__ W,
    const float* __restrict__ bias, const float* __restrict__ res,
    float* __restrict__ C, int M, int N, int K, int n0) {
    __shared__ float As[16][64];
    __shared__ float Bs[16][64];
    int bm = blockIdx.y * 64, bn = n0 + blockIdx.x * 64;
    int tid = threadIdx.x;
    int arow = tid >> 2, acol = (tid & 3) * 4;
    int brow = tid >> 4, bcol = (tid & 15) * 4;
    int tm0 = (tid >> 4) * 4, tn0 = (tid & 15) * 4;
    float acc[4][4];
    #pragma unroll
    for (int i = 0; i < 4; i++)
        #pragma unroll
        for (int j = 0; j < 4; j++) acc[i][j] = 0.f;

    for (int k0 = 0; k0 < K; k0 += 16) {
        uint2 araw = *(const uint2*)(A + (size_t)(bm + arow) * K + k0 + acol);
        __half2 a0 = *(__half2*)&araw.x, a1 = *(__half2*)&araw.y;
        As[acol + 0][arow] = __low2float(a0);
        As[acol + 1][arow] = __high2float(a0);
        As[acol + 2][arow] = __low2float(a1);
        As[acol + 3][arow] = __high2float(a1);
        *(float4*)&Bs[brow][bcol] =
            *(const float4*)&W[(size_t)(k0 + brow) * N + bn + bcol];
        __syncthreads();
        #pragma unroll
        for (int k = 0; k < 16; k++) {
            float ra[4], rb[4];
            *(float4*)(ra) = *(float4*)&As[k][tm0];
            *(float4*)(rb) = *(float4*)&Bs[k][tn0];
            #pragma unroll
            for (int i = 0; i < 4; i++)
                #pragma unroll
                for (int j = 0; j < 4; j++) acc[i][j] += ra[i] * rb[j];
        }
        __syncthreads();
    }
    #pragma unroll
    for (int i = 0; i < 4; i++) {
        size_t rowoff = (size_t)(bm + tm0 + i) * N + bn + tn0;
        float4 rv = *(const float4*)&res[rowoff];
        float4 o;
        o.x = acc[i][0] + bias[bn + tn0 + 0] + rv.x;
        o.y = acc[i][1] + bias[bn + tn0 + 1] + rv.y;
        o.z = acc[i][2] + bias[bn + tn0 + 2] + rv.z;
        o.w = acc[i][3] + bias[bn + tn0 + 3] + rv.w;
        *(float4*)&C[rowoff] = o;
    }
}

// ================= launch =================
extern "C" void kernel_launch(void* const* d_in, const int* in_sizes, int n_in,
                              void* d_out, int out_size) {
    const float* x      = (const float*)d_in[0];
    const float* ln_g   = (const float*)d_in[1];
    const float* ln_b   = (const float*)d_in[2];
    const float* phazor = (const float*)d_in[3];
    const float* phinit = (const float*)d_in[4];
    const float* w1     = (const float*)d_in[5];
    const float* b1     = (const float*)d_in[6];
    const float* w2     = (const float*)d_in[7];
    const float* b2     = (const float*)d_in[8];
    const float* lre    = (const float*)d_in[9];
    const float* lim    = (const float*)d_in[10];
    float* out = (float*)d_out;

    float *y;
    __half *h2h, *act, *w1h, *w2h;
    cudaGetSymbolAddress((void**)&y,   g_y);
    cudaGetSymbolAddress((void**)&h2h, g_h2h);
    cudaGetSymbolAddress((void**)&act, g_act);
    cudaGetSymbolAddress((void**)&w1h, g_w1h);
    cudaGetSymbolAddress((void**)&w2h, g_w2h);

    const int SMEM1 = 3 * (128 + 256) * ROW_H * 2;   // 165888
    const int SMEM2 = 3 * (128 + 64) * ROW_H * 2;    // 82944
    cudaFuncSetAttribute(hgemm<0,256>, cudaFuncAttributeMaxDynamicSharedMemorySize, SMEM1);
    cudaFuncSetAttribute(hgemm<1,64>,  cudaFuncAttributeMaxDynamicSharedMemorySize, SMEM2);

    // second stream, fork/join via events (capture-legal pattern).
    // NOTE: intentionally not destroyed here — destroying capture-referenced
    // objects mid-capture is illegal; kernel_launch host code runs only
    // twice (correctness + capture), so the leak is bounded and harmless.
    cudaStream_t s2;
    cudaStreamCreateWithFlags(&s2, cudaStreamNonBlocking);
    cudaEvent_t evRoot, evT, evH2, evS1, evG1, evS2;
    cudaEventCreateWithFlags(&evRoot, cudaEventDisableTiming);
    cudaEventCreateWithFlags(&evT,    cudaEventDisableTiming);
    cudaEventCreateWithFlags(&evH2,   cudaEventDisableTiming);
    cudaEventCreateWithFlags(&evS1,   cudaEventDisableTiming);
    cudaEventCreateWithFlags(&evG1,   cudaEventDisableTiming);
    cudaEventCreateWithFlags(&evS2,   cudaEventDisableTiming);

    // fork s2 off the captured (default) stream
    cudaEventRecord(evRoot, 0);
    cudaStreamWaitEvent(s2, evRoot, 0);

    // s2: weight transposes (independent of the LN/conv chain)
    transpose_h<<<dim3(DFF_ / 32, DIM_ / 32), dim3(32, 8), 0, s2>>>(w1, w1h, DIM_, DFF_);
    transpose_h<<<dim3(DIM_ / 32, DFF_ / 32), dim3(32, 8), 0, s2>>>(w2, w2h, DFF_, DIM_);
    cudaEventRecord(evT, s2);

    // main: LN1 stats -> conv scan -> LN2
    phazor_prep<<<1, DIM_>>>(phazor, phinit);
    ln_stats<<<NTOK / 8, 256>>>(x);
    conv_phase1<<<B_ * NC, DIM_>>>(x, ln_g, ln_b);
    conv_phase2<<<dim3(B_, DIM_ / 256), 256>>>();
    conv_phase3<<<B_ * NC, DIM_>>>(x, ln_g, ln_b, lre, lim, y);
    ln2_kernel<<<NTOK / 8, 256>>>(y, ln_g, ln_b, h2h);
    cudaEventRecord(evH2, 0);          // h2h (and y) ready

    // s2: GEMM1 FFMA offload (needs h2h + original w1; not the transpose)
    cudaStreamWaitEvent(s2, evH2, 0);
    sgemm_silu<<<dim3((DFF_ - G1_HN) / 128, NTOK / 128), 256, 0, s2>>>(
        h2h, w1, b1, act, NTOK, DFF_, DIM_, G1_HN);
    cudaEventRecord(evS1, s2);

    // main: GEMM1 HMMA part (needs w1h)
    cudaStreamWaitEvent(0, evT, 0);
    hgemm<0,256><<<dim3(G1_HN / 256, NTOK / 128), 256, SMEM1>>>(
        h2h, w1h, b1, nullptr, act, nullptr, NTOK, DFF_, DIM_);
    cudaEventRecord(evG1, 0);

    // s2: GEMM2 FFMA offload (needs full act: hgemm1 + sgemm1)
    cudaStreamWaitEvent(s2, evG1, 0);
    sgemm_res<<<dim3((DIM_ - G2_HN) / 64, NTOK / 64), 256, 0, s2>>>(
        act, w2, b2, y, out, NTOK, DIM_, DFF_, G2_HN);
    cudaEventRecord(evS2, s2);

    // main: GEMM2 HMMA part (needs full act too)
    cudaStreamWaitEvent(0, evS1, 0);
    hgemm<1,64><<<dim3(G2_HN / 64, NTOK / 128), 256, SMEM2>>>(
        act, w2h, b2, y, nullptr, out, NTOK, DIM_, DFF_);

    // join s2 back into the captured stream
    cudaStreamWaitEvent(0, evS2, 0);
}

// round 8
// speedup vs baseline: 1.7356x; 1.7356x over previous
#include <cuda_runtime.h>
#include <cuda_fp16.h>
#include <math.h>
#include <stdint.h>

// Problem constants
#define B_   4
#define L_   2048
#define DIM_ 1024
#define DFF_ 4096
#define NTOK (B_ * L_)            // 8192 rows
#define CS   64                    // conv chunk size
#define NC   (L_ / CS)             // 32 chunks

// -------- scratch (static __device__ — no allocations allowed) --------
__device__ float   g_y  [(size_t)NTOK * DIM_];
__device__ __half  g_h2h[(size_t)NTOK * DIM_];   // LN2 out, fp16
__device__ __half  g_act[(size_t)NTOK * DFF_];   // SiLU out, fp16
__device__ __half  g_w1h[(size_t)DFF_ * DIM_];   // w1^T fp16 [N=4096,K=1024]
__device__ __half  g_w2h[(size_t)DIM_ * DFF_];   // w2^T fp16 [N=1024,K=4096]
__device__ float2  g_stat[NTOK];                 // LN1 (mu, rstd) per row
__device__ float2  g_carry[B_ * NC * DIM_];
__device__ float2  g_zin  [B_ * NC * DIM_];
__device__ float2  g_p    [DIM_];
__device__ float2  g_pinit[DIM_];
__device__ float2  g_p64  [DIM_];

// ================= helpers =================
__device__ __forceinline__ uint32_t smem_u32(const void* p) {
    return (uint32_t)__cvta_generic_to_shared(p);
}
__device__ __forceinline__ void cp_async16(uint32_t saddr, const void* gptr) {
    asm volatile("cp.async.cg.shared.global [%0], [%1], 16;" :: "r"(saddr), "l"(gptr));
}
#define CP_COMMIT()  asm volatile("cp.async.commit_group;" ::: "memory")
#define CP_WAIT(n)   asm volatile("cp.async.wait_group %0;" :: "n"(n) : "memory")
#define LDSM_X4(r0, r1, r2, r3, addr) \
    asm volatile("ldmatrix.sync.aligned.m8n8.x4.shared.b16 {%0,%1,%2,%3}, [%4];" \
                 : "=r"(r0), "=r"(r1), "=r"(r2), "=r"(r3) : "r"(addr))

// ================= phazor precompute =================
__global__ void phazor_prep(const float* __restrict__ phazor,
                            const float* __restrict__ phazor_init) {
    int d = blockIdx.x * blockDim.x + threadIdx.x;
    if (d >= DIM_) return;
    float pr = phazor[2 * d], pim = phazor[2 * d + 1];
    float pa = sqrtf(pr * pr + pim * pim);
    float s = expf(-pa) / pa;
    float2 p = make_float2(pr * s, pim * s);
    g_p[d] = p;
    g_pinit[d] = make_float2(phazor_init[2 * d], phazor_init[2 * d + 1]);
    float2 q = p;
    #pragma unroll
    for (int i = 0; i < 6; i++) {
        float nr = q.x * q.x - q.y * q.y;
        q.y = 2.f * q.x * q.y;
        q.x = nr;
    }
    g_p64[d] = q;
}

// ========== LN1 stats: warp per row ==========
__global__ void ln_stats(const float* __restrict__ x) {
    int row = blockIdx.x * 8 + (threadIdx.x >> 5);
    int lane = threadIdx.x & 31;
    const float4* xr = (const float4*)(x + (size_t)row * DIM_);
    float s = 0.f, ss = 0.f;
    #pragma unroll
    for (int i = 0; i < 8; i++) {
        float4 v = xr[lane + 32 * i];
        s  += v.x + v.y + v.z + v.w;
        ss += v.x * v.x + v.y * v.y + v.z * v.z + v.w * v.w;
    }
    #pragma unroll
    for (int o = 16; o > 0; o >>= 1) {
        s  += __shfl_xor_sync(0xffffffffu, s, o);
        ss += __shfl_xor_sync(0xffffffffu, ss, o);
    }
    if (lane == 0) {
        float mu = s * (1.f / DIM_);
        float var = ss * (1.f / DIM_) - mu * mu;
        g_stat[row] = make_float2(mu, rsqrtf(var + 1e-5f));
    }
}

// ========== LN2 (warp per row, fp32 in -> fp16 out) ==========
__global__ void ln2_kernel(const float* __restrict__ x, const float* __restrict__ g,
                           const float* __restrict__ bb, __half* __restrict__ out16) {
    int row = blockIdx.x * 8 + (threadIdx.x >> 5);
    int lane = threadIdx.x & 31;
    const float4* xr = (const float4*)(x + (size_t)row * DIM_);
    float4 vv[8];
    float s = 0.f, ss = 0.f;
    #pragma unroll
    for (int i = 0; i < 8; i++) {
        float4 v = xr[lane + 32 * i];
        vv[i] = v;
        s  += v.x + v.y + v.z + v.w;
        ss += v.x * v.x + v.y * v.y + v.z * v.z + v.w * v.w;
    }
    #pragma unroll
    for (int o = 16; o > 0; o >>= 1) {
        s  += __shfl_xor_sync(0xffffffffu, s, o);
        ss += __shfl_xor_sync(0xffffffffu, ss, o);
    }
    float mu  = s * (1.f / DIM_);
    float var = ss * (1.f / DIM_) - mu * mu;
    float inv = rsqrtf(var + 1e-5f);
    #pragma unroll
    for (int i = 0; i < 8; i++) {
        float4 gv = ((const float4*)g)[lane + 32 * i];
        float4 bv = ((const float4*)bb)[lane + 32 * i];
        float4 v = vv[i];
        __half2 h0 = __floats2half2_rn((v.x - mu) * inv * gv.x + bv.x,
                                       (v.y - mu) * inv * gv.y + bv.y);
        __half2 h1 = __floats2half2_rn((v.z - mu) * inv * gv.z + bv.z,
                                       (v.w - mu) * inv * gv.w + bv.w);
        uint2 pk = make_uint2(*(uint32_t*)&h0, *(uint32_t*)&h1);
        *(uint2*)(out16 + (size_t)row * DIM_ + (lane + 32 * i) * 4) = pk;
    }
}

// ================= spiral conv: 3-phase chunked scan =================
__global__ void conv_phase1(const float* __restrict__ x, const float* __restrict__ lng,
                            const float* __restrict__ lnb) {
    int b = blockIdx.x >> 5, c = blockIdx.x & 31, d = threadIdx.x;
    float2 p = g_p[d];
    float gd = lng[d], bd = lnb[d];
    float zr = 0.f, zi = 0.f;
    int row0 = b * L_ + c * CS;
    const float* xp = x + (size_t)row0 * DIM_ + d;
    #pragma unroll 4
    for (int j = 0; j < CS; j++) {
        float2 st = g_stat[row0 + j];
        float hv = (xp[(size_t)j * DIM_] - st.x) * st.y * gd + bd;
        float nr = p.x * zr - p.y * zi + hv;
        zi = p.x * zi + p.y * zr;
        zr = nr;
    }
    g_carry[(b * NC + c) * DIM_ + d] = make_float2(zr, zi);
}

__global__ void conv_phase2() {
    int b = blockIdx.x;
    int d = blockIdx.y * 256 + threadIdx.x;
    float2 pc = g_p64[d];
    float2 cv[NC];
    #pragma unroll
    for (int c = 0; c < NC; c++) cv[c] = g_carry[(b * NC + c) * DIM_ + d];
    float zr = 0.f, zi = 0.f;
    #pragma unroll
    for (int c = 0; c < NC; c++) {
        g_zin[(b * NC + c) * DIM_ + d] = make_float2(zr, zi);
        float nr = pc.x * zr - pc.y * zi + cv[c].x;
        zi = pc.x * zi + pc.y * zr + cv[c].y;
        zr = nr;
    }
}

__global__ void conv_phase3(const float* __restrict__ x, const float* __restrict__ lng,
                            const float* __restrict__ lnb,
                            const float* __restrict__ lre, const float* __restrict__ lim,
                            float* __restrict__ y) {
    int b = blockIdx.x >> 5, c = blockIdx.x & 31, d = threadIdx.x;
    float2 p  = g_p[d];
    float2 pi = g_pinit[d];
    float2 pc = g_p64[d];
    float2 z  = g_zin[(b * NC + c) * DIM_ + d];
    float gd = lng[d], bd = lnb[d];
    float twr = 1.f, twi = 0.f;
    for (int i = 0; i < c; i++) {
        float nr = twr * pc.x - twi * pc.y;
        twi = twr * pc.y + twi * pc.x;
        twr = nr;
    }
    float pwr = twr * p.x - twi * p.y;
    float pwi = twr * p.y + twi * p.x;
    float lr = lre[b * DIM_ + d], li = lim[b * DIM_ + d];
    int row0 = b * L_ + c * CS;
    size_t base = (size_t)row0 * DIM_ + d;
    #pragma unroll 4
    for (int j = 0; j < CS; j++) {
        float xv = x[base + (size_t)j * DIM_];
        float2 st = g_stat[row0 + j];
        float hv = (xv - st.x) * st.y * gd + bd;
        float nr = p.x * z.x - p.y * z.y + hv;
        z.y = p.x * z.y + p.y * z.x;
        z.x = nr;
        float val = pi.x * z.x - pi.y * z.y + lr * pwr - li * pwi;
        y[base + (size_t)j * DIM_] = val + xv;
        float npr = pwr * p.x - pwi * p.y;
        pwi = pwr * p.y + pwi * p.x;
        pwr = npr;
    }
}

// ======== weight transpose + cast ([K,N] fp32 -> [N,K] fp16) ========
__global__ void transpose_h(const float* __restrict__ in, __half* __restrict__ out,
                            int R, int Ccols) {
    __shared__ float t[32][33];
    int bx = blockIdx.x * 32, by = blockIdx.y * 32;
    int tx = threadIdx.x, ty = threadIdx.y;
    #pragma unroll
    for (int j = 0; j < 32; j += 8)
        t[ty + j][tx] = in[(size_t)(by + ty + j) * Ccols + bx + tx];
    __syncthreads();
    #pragma unroll
    for (int j = 0; j < 32; j += 8)
        out[(size_t)(bx + ty + j) * R + by + tx] = __float2half(t[tx][ty + j]);
}

// ======= fp16 tensor-core GEMM (mma.sync m16n8k16 + ldmatrix) =======
// CTA tile 128 x CTN (CTN=256: 1 CTA/SM; CTN=128: 2 CTA/SM), BK=32,
// 8 warps in 2x4 grid, warp tile 64 x (CTN/4), 3-stage ring, 1 barrier/kt.
// EPI==0: act(half) = silu(acc + bias);  EPI==1: out(f32) = acc + bias + res
#define TBK 32
#define ROW_H 72                         // padded stride in halves (144B)

template <int EPI, int CTN>
__global__ __launch_bounds__(256, (CTN == 128) ? 2 : 1) void hgemm(
    const __half* __restrict__ A, const __half* __restrict__ Bt,
    const float* __restrict__ bias, const float* __restrict__ res,
    __half* __restrict__ Ch, float* __restrict__ Cf, int M, int N, int K) {
    constexpr int WNW = CTN / 4;         // warp n-width: 64 or 32
    constexpr int NT  = WNW / 8;         // n-subtiles: 8 or 4
    constexpr int NP  = NT / 2;          // ldmatrix x4 B loads: 4 or 2
    constexpr int BCH = CTN / 64;        // B 16B-chunks per thread: 4 or 2
    constexpr int A_H = 128 * ROW_H;
    constexpr int STG = (128 + CTN) * ROW_H;

    extern __shared__ __half sm[];
    int tid = threadIdx.x, wid = tid >> 5, lane = tid & 31;
    int g = lane >> 2, l4 = lane & 3;
    int wm = (wid & 1) * 64;
    int wn = (wid >> 1) * WNW;
    int bm = blockIdx.y * 128, bn = blockIdx.x * CTN;
    const int NK = K / TBK;

    int mat = lane >> 3, rr = lane & 7;
    uint32_t aoff[4], boff[NP];
    #pragma unroll
    for (int mt = 0; mt < 4; mt++)
        aoff[mt] = (uint32_t)((wm + mt * 16 + (mat & 1) * 8 + rr) * 144 + (mat >> 1) * 16);
    #pragma unroll
    for (int np = 0; np < NP; np++)
        boff[np] = (uint32_t)((wn + np * 16 + (mat >> 1) * 8 + rr) * 144 + (mat & 1) * 16);

    auto load_stage = [&](int s, int k0) {
        uint32_t base = smem_u32(sm + (size_t)s * STG);
        #pragma unroll
        for (int i = 0; i < 2; i++) {
            int c = tid + i * 256;
            int row = c >> 2, kc = c & 3;
            cp_async16(base + row * 144 + kc * 16,
                       A + (size_t)(bm + row) * K + k0 + kc * 8);
        }
        uint32_t bb = base + A_H * 2;
        #pragma unroll
        for (int i = 0; i < BCH; i++) {
            int c = tid + i * 256;
            int row = c >> 2, kc = c & 3;
            cp_async16(bb + row * 144 + kc * 16,
                       Bt + (size_t)(bn + row) * K + k0 + kc * 8);
        }
    };

    float acc[4][NT][4];
    #pragma unroll
    for (int i = 0; i < 4; i++)
        #pragma unroll
        for (int j = 0; j < NT; j++)
            #pragma unroll
            for (int r = 0; r < 4; r++) acc[i][j][r] = 0.f;

    load_stage(0, 0);       CP_COMMIT();
    load_stage(1, TBK);     CP_COMMIT();

    for (int kt = 0; kt < NK; kt++) {
        if (kt + 1 < NK) CP_WAIT(1); else CP_WAIT(0);
        __syncthreads();
        // barrier above guarantees stage (kt-1)%3 == (kt+2)%3 is free
        if (kt + 2 < NK) load_stage((kt + 2) % 3, (kt + 2) * TBK);
        CP_COMMIT();
        uint32_t sa = smem_u32(sm + (size_t)(kt % 3) * STG);
        uint32_t sb = sa + A_H * 2;
        #pragma unroll
        for (int ks = 0; ks < TBK; ks += 16) {
            uint32_t af[4][4], bf[NT][2];
            #pragma unroll
            for (int mt = 0; mt < 4; mt++)
                LDSM_X4(af[mt][0], af[mt][1], af[mt][2], af[mt][3],
                        sa + aoff[mt] + ks * 2);
            #pragma unroll
            for (int np = 0; np < NP; np++)
                LDSM_X4(bf[2 * np][0], bf[2 * np][1], bf[2 * np + 1][0], bf[2 * np + 1][1],
                        sb + boff[np] + ks * 2);
            #pragma unroll
            for (int mt = 0; mt < 4; mt++)
                #pragma unroll
                for (int nt = 0; nt < NT; nt++) {
                    asm volatile(
                        "mma.sync.aligned.m16n8k16.row.col.f32.f16.f16.f32 "
                        "{%0,%1,%2,%3}, {%4,%5,%6,%7}, {%8,%9}, {%0,%1,%2,%3};"
                        : "+f"(acc[mt][nt][0]), "+f"(acc[mt][nt][1]),
                          "+f"(acc[mt][nt][2]), "+f"(acc[mt][nt][3])
                        : "r"(af[mt][0]), "r"(af[mt][1]), "r"(af[mt][2]), "r"(af[mt][3]),
                          "r"(bf[nt][0]), "r"(bf[nt][1]));
                }
        }
    }

    // ---- epilogue ----
    #pragma unroll
    for (int mt = 0; mt < 4; mt++) {
        int r0 = bm + wm + mt * 16 + g;
        #pragma unroll
        for (int nt = 0; nt < NT; nt++) {
            int col = bn + wn + nt * 8 + 2 * l4;
            float bv0 = bias[col], bv1 = bias[col + 1];
            #pragma unroll
            for (int h = 0; h < 2; h++) {
                int row = r0 + h * 8;
                size_t off = (size_t)row * N + col;
                float v0 = acc[mt][nt][2 * h + 0] + bv0;
                float v1 = acc[mt][nt][2 * h + 1] + bv1;
                if (EPI == 0) {
                    v0 = v0 / (1.f + expf(-v0));
                    v1 = v1 / (1.f + expf(-v1));
                    __half2 hv = __floats2half2_rn(v0, v1);
                    *(__half2*)&Ch[off] = hv;
                } else {
                    v0 += res[off];
                    v1 += res[off + 1];
                    *(float2*)&Cf[off] = make_float2(v0, v1);
                }
            }
        }
    }
}

// ================= launch =================
extern "C" void kernel_launch(void* const* d_in, const int* in_sizes, int n_in,
                              void* d_out, int out_size) {
    const float* x      = (const float*)d_in[0];
    const float* ln_g   = (const float*)d_in[1];
    const float* ln_b   = (const float*)d_in[2];
    const float* phazor = (const float*)d_in[3];
    const float* phinit = (const float*)d_in[4];
    const float* w1     = (const float*)d_in[5];
    const float* b1     = (const float*)d_in[6];
    const float* w2     = (const float*)d_in[7];
    const float* b2     = (const float*)d_in[8];
    const float* lre    = (const float*)d_in[9];
    const float* lim    = (const float*)d_in[10];
    float* out = (float*)d_out;

    float *y;
    __half *h2h, *act, *w1h, *w2h;
    cudaGetSymbolAddress((void**)&y,   g_y);
    cudaGetSymbolAddress((void**)&h2h, g_h2h);
    cudaGetSymbolAddress((void**)&act, g_act);
    cudaGetSymbolAddress((void**)&w1h, g_w1h);
    cudaGetSymbolAddress((void**)&w2h, g_w2h);

    const int SMEM1 = 3 * (128 + 256) * ROW_H * 2;   // 165888
    const int SMEM2 = 3 * (128 + 128) * ROW_H * 2;   // 110592
    cudaFuncSetAttribute(hgemm<0,256>, cudaFuncAttributeMaxDynamicSharedMemorySize, SMEM1);
    cudaFuncSetAttribute(hgemm<1,128>, cudaFuncAttributeMaxDynamicSharedMemorySize, SMEM2);

    // fork a second stream for the weight transposes only; they overlap the
    // LN/conv chain and join before GEMM1. (Objects persist — creating them
    // is capture-legal; destroying capture-referenced objects is not. Host
    // code here runs only for correctness + capture, so the leak is bounded.)
    cudaStream_t s2;
    cudaStreamCreateWithFlags(&s2, cudaStreamNonBlocking);
    cudaEvent_t evRoot, evT;
    cudaEventCreateWithFlags(&evRoot, cudaEventDisableTiming);
    cudaEventCreateWithFlags(&evT,    cudaEventDisableTiming);

    cudaEventRecord(evRoot, 0);
    cudaStreamWaitEvent(s2, evRoot, 0);

    // s2: weight transposes (independent of LN/conv chain)
    transpose_h<<<dim3(DFF_ / 32, DIM_ / 32), dim3(32, 8), 0, s2>>>(w1, w1h, DIM_, DFF_);
    transpose_h<<<dim3(DIM_ / 32, DFF_ / 32), dim3(32, 8), 0, s2>>>(w2, w2h, DFF_, DIM_);
    cudaEventRecord(evT, s2);

    // main: LN1 stats -> conv scan -> LN2
    phazor_prep<<<1, DIM_>>>(phazor, phinit);
    ln_stats<<<NTOK / 8, 256>>>(x);
    conv_phase1<<<B_ * NC, DIM_>>>(x, ln_g, ln_b);
    conv_phase2<<<dim3(B_, DIM_ / 256), 256>>>();
    conv_phase3<<<B_ * NC, DIM_>>>(x, ln_g, ln_b, lre, lim, y);
    ln2_kernel<<<NTOK / 8, 256>>>(y, ln_g, ln_b, h2h);

    // join: GEMMs need the transposed weights
    cudaStreamWaitEvent(0, evT, 0);

    dim3 g1(DFF_ / 256, NTOK / 128);   // 16 x 64
    hgemm<0,256><<<g1, 256, SMEM1>>>(h2h, w1h, b1, nullptr, act, nullptr, NTOK, DFF_, DIM_);
    dim3 g2(DIM_ / 128, NTOK / 128);   // 8 x 64
    hgemm<1,128><<<g2, 256, SMEM2>>>(act, w2h, b2, y, nullptr, out, NTOK, DIM_, DFF_);
}

// round 9
// speedup vs baseline: 1.8902x; 1.0891x over previous
#include <cuda_runtime.h>
#include <cuda_fp16.h>
#include <math.h>
#include <stdint.h>

// Problem constants
#define B_   4
#define L_   2048
#define DIM_ 1024
#define DFF_ 4096
#define NTOK (B_ * L_)            // 8192 rows
#define CS   64                    // conv chunk size
#define NC   (L_ / CS)             // 32 chunks

// -------- scratch (static __device__ — no allocations allowed) --------
__device__ float   g_y  [(size_t)NTOK * DIM_];
__device__ __half  g_h2h[(size_t)NTOK * DIM_];   // LN2 out, fp16
__device__ __half  g_act[(size_t)NTOK * DFF_];   // SiLU out, fp16
__device__ __half  g_w1h[(size_t)DFF_ * DIM_];   // w1^T fp16 [N=4096,K=1024]
__device__ __half  g_w2h[(size_t)DIM_ * DFF_];   // w2^T fp16 [N=1024,K=4096]
__device__ float2  g_stat[NTOK];                 // LN1 (mu, rstd) per row
__device__ float2  g_carry[B_ * NC * DIM_];
__device__ float2  g_zin  [B_ * NC * DIM_];
__device__ float2  g_p    [DIM_];
__device__ float2  g_pinit[DIM_];
__device__ float2  g_p64  [DIM_];

// ================= helpers =================
__device__ __forceinline__ uint32_t smem_u32(const void* p) {
    return (uint32_t)__cvta_generic_to_shared(p);
}
__device__ __forceinline__ void cp_async16(uint32_t saddr, const void* gptr) {
    asm volatile("cp.async.cg.shared.global [%0], [%1], 16;" :: "r"(saddr), "l"(gptr));
}
#define CP_COMMIT()  asm volatile("cp.async.commit_group;" ::: "memory")
#define CP_WAIT(n)   asm volatile("cp.async.wait_group %0;" :: "n"(n) : "memory")
#define LDSM_X4(r0, r1, r2, r3, addr) \
    asm volatile("ldmatrix.sync.aligned.m8n8.x4.shared.b16 {%0,%1,%2,%3}, [%4];" \
                 : "=r"(r0), "=r"(r1), "=r"(r2), "=r"(r3) : "r"(addr))

// ================= phazor precompute =================
__global__ void phazor_prep(const float* __restrict__ phazor,
                            const float* __restrict__ phazor_init) {
    int d = blockIdx.x * blockDim.x + threadIdx.x;
    if (d >= DIM_) return;
    float pr = phazor[2 * d], pim = phazor[2 * d + 1];
    float pa = sqrtf(pr * pr + pim * pim);
    float s = expf(-pa) / pa;
    float2 p = make_float2(pr * s, pim * s);
    g_p[d] = p;
    g_pinit[d] = make_float2(phazor_init[2 * d], phazor_init[2 * d + 1]);
    float2 q = p;
    #pragma unroll
    for (int i = 0; i < 6; i++) {
        float nr = q.x * q.x - q.y * q.y;
        q.y = 2.f * q.x * q.y;
        q.x = nr;
    }
    g_p64[d] = q;
}

// ========== LN2 (warp per row, fp32 in -> fp16 out) ==========
__global__ void ln2_kernel(const float* __restrict__ x, const float* __restrict__ g,
                           const float* __restrict__ bb, __half* __restrict__ out16) {
    int row = blockIdx.x * 8 + (threadIdx.x >> 5);
    int lane = threadIdx.x & 31;
    const float4* xr = (const float4*)(x + (size_t)row * DIM_);
    float4 vv[8];
    float s = 0.f, ss = 0.f;
    #pragma unroll
    for (int i = 0; i < 8; i++) {
        float4 v = xr[lane + 32 * i];
        vv[i] = v;
        s  += v.x + v.y + v.z + v.w;
        ss += v.x * v.x + v.y * v.y + v.z * v.z + v.w * v.w;
    }
    #pragma unroll
    for (int o = 16; o > 0; o >>= 1) {
        s  += __shfl_xor_sync(0xffffffffu, s, o);
        ss += __shfl_xor_sync(0xffffffffu, ss, o);
    }
    float mu  = s * (1.f / DIM_);
    float var = ss * (1.f / DIM_) - mu * mu;
    float inv = rsqrtf(var + 1e-5f);
    #pragma unroll
    for (int i = 0; i < 8; i++) {
        float4 gv = ((const float4*)g)[lane + 32 * i];
        float4 bv = ((const float4*)bb)[lane + 32 * i];
        float4 v = vv[i];
        __half2 h0 = __floats2half2_rn((v.x - mu) * inv * gv.x + bv.x,
                                       (v.y - mu) * inv * gv.y + bv.y);
        __half2 h1 = __floats2half2_rn((v.z - mu) * inv * gv.z + bv.z,
                                       (v.w - mu) * inv * gv.w + bv.w);
        uint2 pk = make_uint2(*(uint32_t*)&h0, *(uint32_t*)&h1);
        *(uint2*)(out16 + (size_t)row * DIM_ + (lane + 32 * i) * 4) = pk;
    }
}

// ========== conv phase1 (fused LN1 stats + scan carry) ==========
// Block (b,c): 64 rows x 1024 dims, 1024 threads.
// Pass A: thread t = 16*j + k sums row j (16 threads/row, float4 coalesced),
//         half-warp shfl reduce -> smem stats + g_stat.
// Pass B: thread d scans its column (x re-read from hot L2).
__global__ void conv_phase1(const float* __restrict__ x, const float* __restrict__ lng,
                            const float* __restrict__ lnb) {
    __shared__ float2 sh_stat[CS];
    int b = blockIdx.x >> 5, c = blockIdx.x & 31;
    int tid = threadIdx.x;
    int row0 = b * L_ + c * CS;

    // ---- pass A: stats for the block's 64 rows ----
    {
        int j = tid >> 4, k = tid & 15;
        const float4* xr = (const float4*)(x + (size_t)(row0 + j) * DIM_);
        float s = 0.f, ss = 0.f;
        #pragma unroll
        for (int i = 0; i < 16; i++) {
            float4 v = xr[k + 16 * i];
            s  += v.x + v.y + v.z + v.w;
            ss += v.x * v.x + v.y * v.y + v.z * v.z + v.w * v.w;
        }
        #pragma unroll
        for (int o = 8; o > 0; o >>= 1) {
            s  += __shfl_xor_sync(0xffffffffu, s, o);
            ss += __shfl_xor_sync(0xffffffffu, ss, o);
        }
        if (k == 0) {
            float mu = s * (1.f / DIM_);
            float var = ss * (1.f / DIM_) - mu * mu;
            float2 st = make_float2(mu, rsqrtf(var + 1e-5f));
            sh_stat[j] = st;
            g_stat[row0 + j] = st;   // for conv_phase3
        }
    }
    __syncthreads();

    // ---- pass B: scan ----
    int d = tid;
    float2 p = g_p[d];
    float gd = lng[d], bd = lnb[d];
    float zr = 0.f, zi = 0.f;
    const float* xp = x + (size_t)row0 * DIM_ + d;
    #pragma unroll 4
    for (int j = 0; j < CS; j++) {
        float2 st = sh_stat[j];
        float hv = (xp[(size_t)j * DIM_] - st.x) * st.y * gd + bd;
        float nr = p.x * zr - p.y * zi + hv;
        zi = p.x * zi + p.y * zr;
        zr = nr;
    }
    g_carry[(b * NC + c) * DIM_ + d] = make_float2(zr, zi);
}

__global__ void conv_phase2() {
    int b = blockIdx.x;
    int d = blockIdx.y * 256 + threadIdx.x;
    float2 pc = g_p64[d];
    float2 cv[NC];
    #pragma unroll
    for (int c = 0; c < NC; c++) cv[c] = g_carry[(b * NC + c) * DIM_ + d];
    float zr = 0.f, zi = 0.f;
    #pragma unroll
    for (int c = 0; c < NC; c++) {
        g_zin[(b * NC + c) * DIM_ + d] = make_float2(zr, zi);
        float nr = pc.x * zr - pc.y * zi + cv[c].x;
        zi = pc.x * zi + pc.y * zr + cv[c].y;
        zr = nr;
    }
}

__global__ void conv_phase3(const float* __restrict__ x, const float* __restrict__ lng,
                            const float* __restrict__ lnb,
                            const float* __restrict__ lre, const float* __restrict__ lim,
                            float* __restrict__ y) {
    int b = blockIdx.x >> 5, c = blockIdx.x & 31, d = threadIdx.x;
    float2 p  = g_p[d];
    float2 pi = g_pinit[d];
    float2 pc = g_p64[d];
    float2 z  = g_zin[(b * NC + c) * DIM_ + d];
    float gd = lng[d], bd = lnb[d];
    float twr = 1.f, twi = 0.f;
    for (int i = 0; i < c; i++) {
        float nr = twr * pc.x - twi * pc.y;
        twi = twr * pc.y + twi * pc.x;
        twr = nr;
    }
    float pwr = twr * p.x - twi * p.y;
    float pwi = twr * p.y + twi * p.x;
    float lr = lre[b * DIM_ + d], li = lim[b * DIM_ + d];
    int row0 = b * L_ + c * CS;
    size_t base = (size_t)row0 * DIM_ + d;
    #pragma unroll 4
    for (int j = 0; j < CS; j++) {
        float xv = x[base + (size_t)j * DIM_];
        float2 st = g_stat[row0 + j];
        float hv = (xv - st.x) * st.y * gd + bd;
        float nr = p.x * z.x - p.y * z.y + hv;
        z.y = p.x * z.y + p.y * z.x;
        z.x = nr;
        float val = pi.x * z.x - pi.y * z.y + lr * pwr - li * pwi;
        y[base + (size_t)j * DIM_] = val + xv;
        float npr = pwr * p.x - pwi * p.y;
        pwi = pwr * p.y + pwi * p.x;
        pwr = npr;
    }
}

// ======== weight transpose + cast ([K,N] fp32 -> [N,K] fp16) ========
__global__ void transpose_h(const float* __restrict__ in, __half* __restrict__ out,
                            int R, int Ccols) {
    __shared__ float t[32][33];
    int bx = blockIdx.x * 32, by = blockIdx.y * 32;
    int tx = threadIdx.x, ty = threadIdx.y;
    #pragma unroll
    for (int j = 0; j < 32; j += 8)
        t[ty + j][tx] = in[(size_t)(by + ty + j) * Ccols + bx + tx];
    __syncthreads();
    #pragma unroll
    for (int j = 0; j < 32; j += 8)
        out[(size_t)(bx + ty + j) * R + by + tx] = __float2half(t[tx][ty + j]);
}

// ======= fp16 tensor-core GEMM (mma.sync m16n8k16 + ldmatrix) =======
// CTA tile 128 x 128, 2 CTAs/SM, BK=32, 8 warps (2x4), warp tile 64x32,
// 3-stage cp.async ring, 1 barrier per k-tile.
// EPI==0: act(half) = silu(acc + bias);  EPI==1: out(f32) = acc + bias + res
#define TBK 32
#define ROW_H 72                         // padded stride in halves (144B)
#define CTN 128
#define GEMM_SMEM (3 * (128 + CTN) * ROW_H * 2)   // 110592

template <int EPI>
__global__ __launch_bounds__(256, 2) void hgemm(
    const __half* __restrict__ A, const __half* __restrict__ Bt,
    const float* __restrict__ bias, const float* __restrict__ res,
    __half* __restrict__ Ch, float* __restrict__ Cf, int M, int N, int K) {
    constexpr int WNW = CTN / 4;         // 32
    constexpr int NT  = WNW / 8;         // 4
    constexpr int NP  = NT / 2;          // 2
    constexpr int BCH = CTN / 64;        // 2
    constexpr int A_H = 128 * ROW_H;
    constexpr int STG = (128 + CTN) * ROW_H;

    extern __shared__ __half sm[];
    int tid = threadIdx.x, wid = tid >> 5, lane = tid & 31;
    int g = lane >> 2, l4 = lane & 3;
    int wm = (wid & 1) * 64;
    int wn = (wid >> 1) * WNW;
    int bm = blockIdx.y * 128, bn = blockIdx.x * CTN;
    const int NK = K / TBK;

    int mat = lane >> 3, rr = lane & 7;
    uint32_t aoff[4], boff[NP];
    #pragma unroll
    for (int mt = 0; mt < 4; mt++)
        aoff[mt] = (uint32_t)((wm + mt * 16 + (mat & 1) * 8 + rr) * 144 + (mat >> 1) * 16);
    #pragma unroll
    for (int np = 0; np < NP; np++)
        boff[np] = (uint32_t)((wn + np * 16 + (mat >> 1) * 8 + rr) * 144 + (mat & 1) * 16);

    auto load_stage = [&](int s, int k0) {
        uint32_t base = smem_u32(sm + (size_t)s * STG);
        #pragma unroll
        for (int i = 0; i < 2; i++) {
            int c = tid + i * 256;
            int row = c >> 2, kc = c & 3;
            cp_async16(base + row * 144 + kc * 16,
                       A + (size_t)(bm + row) * K + k0 + kc * 8);
        }
        uint32_t bb = base + A_H * 2;
        #pragma unroll
        for (int i = 0; i < BCH; i++) {
            int c = tid + i * 256;
            int row = c >> 2, kc = c & 3;
            cp_async16(bb + row * 144 + kc * 16,
                       Bt + (size_t)(bn + row) * K + k0 + kc * 8);
        }
    };

    float acc[4][NT][4];
    #pragma unroll
    for (int i = 0; i < 4; i++)
        #pragma unroll
        for (int j = 0; j < NT; j++)
            #pragma unroll
            for (int r = 0; r < 4; r++) acc[i][j][r] = 0.f;

    load_stage(0, 0);       CP_COMMIT();
    load_stage(1, TBK);     CP_COMMIT();

    for (int kt = 0; kt < NK; kt++) {
        if (kt + 1 < NK) CP_WAIT(1); else CP_WAIT(0);
        __syncthreads();
        if (kt + 2 < NK) load_stage((kt + 2) % 3, (kt + 2) * TBK);
        CP_COMMIT();
        uint32_t sa = smem_u32(sm + (size_t)(kt % 3) * STG);
        uint32_t sb = sa + A_H * 2;
        #pragma unroll
        for (int ks = 0; ks < TBK; ks += 16) {
            uint32_t af[4][4], bf[NT][2];
            #pragma unroll
            for (int mt = 0; mt < 4; mt++)
                LDSM_X4(af[mt][0], af[mt][1], af[mt][2], af[mt][3],
                        sa + aoff[mt] + ks * 2);
            #pragma unroll
            for (int np = 0; np < NP; np++)
                LDSM_X4(bf[2 * np][0], bf[2 * np][1], bf[2 * np + 1][0], bf[2 * np + 1][1],
                        sb + boff[np] + ks * 2);
            #pragma unroll
            for (int mt = 0; mt < 4; mt++)
                #pragma unroll
                for (int nt = 0; nt < NT; nt++) {
                    asm volatile(
                        "mma.sync.aligned.m16n8k16.row.col.f32.f16.f16.f32 "
                        "{%0,%1,%2,%3}, {%4,%5,%6,%7}, {%8,%9}, {%0,%1,%2,%3};"
                        : "+f"(acc[mt][nt][0]), "+f"(acc[mt][nt][1]),
                          "+f"(acc[mt][nt][2]), "+f"(acc[mt][nt][3])
                        : "r"(af[mt][0]), "r"(af[mt][1]), "r"(af[mt][2]), "r"(af[mt][3]),
                          "r"(bf[nt][0]), "r"(bf[nt][1]));
                }
        }
    }

    // ---- epilogue ----
    #pragma unroll
    for (int mt = 0; mt < 4; mt++) {
        int r0 = bm + wm + mt * 16 + g;
        #pragma unroll
        for (int nt = 0; nt < NT; nt++) {
            int col = bn + wn + nt * 8 + 2 * l4;
            float bv0 = bias[col], bv1 = bias[col + 1];
            #pragma unroll
            for (int h = 0; h < 2; h++) {
                int row = r0 + h * 8;
                size_t off = (size_t)row * N + col;
                float v0 = acc[mt][nt][2 * h + 0] + bv0;
                float v1 = acc[mt][nt][2 * h + 1] + bv1;
                if (EPI == 0) {
                    v0 = v0 / (1.f + expf(-v0));
                    v1 = v1 / (1.f + expf(-v1));
                    __half2 hv = __floats2half2_rn(v0, v1);
                    *(__half2*)&Ch[off] = hv;
                } else {
                    v0 += res[off];
                    v1 += res[off + 1];
                    *(float2*)&Cf[off] = make_float2(v0, v1);
                }
            }
        }
    }
}

// ================= launch =================
extern "C" void kernel_launch(void* const* d_in, const int* in_sizes, int n_in,
                              void* d_out, int out_size) {
    const float* x      = (const float*)d_in[0];
    const float* ln_g   = (const float*)d_in[1];
    const float* ln_b   = (const float*)d_in[2];
    const float* phazor = (const float*)d_in[3];
    const float* phinit = (const float*)d_in[4];
    const float* w1     = (const float*)d_in[5];
    const float* b1     = (const float*)d_in[6];
    const float* w2     = (const float*)d_in[7];
    const float* b2     = (const float*)d_in[8];
    const float* lre    = (const float*)d_in[9];
    const float* lim    = (const float*)d_in[10];
    float* out = (float*)d_out;

    float *y;
    __half *h2h, *act, *w1h, *w2h;
    cudaGetSymbolAddress((void**)&y,   g_y);
    cudaGetSymbolAddress((void**)&h2h, g_h2h);
    cudaGetSymbolAddress((void**)&act, g_act);
    cudaGetSymbolAddress((void**)&w1h, g_w1h);
    cudaGetSymbolAddress((void**)&w2h, g_w2h);

    cudaFuncSetAttribute(hgemm<0>, cudaFuncAttributeMaxDynamicSharedMemorySize, GEMM_SMEM);
    cudaFuncSetAttribute(hgemm<1>, cudaFuncAttributeMaxDynamicSharedMemorySize, GEMM_SMEM);

    // fork a second stream for the weight transposes; they overlap the
    // LN/conv chain and join before GEMM1. (Objects persist — bounded leak;
    // destroying capture-referenced objects would be illegal.)
    cudaStream_t s2;
    cudaStreamCreateWithFlags(&s2, cudaStreamNonBlocking);
    cudaEvent_t evRoot, evT;
    cudaEventCreateWithFlags(&evRoot, cudaEventDisableTiming);
    cudaEventCreateWithFlags(&evT,    cudaEventDisableTiming);

    cudaEventRecord(evRoot, 0);
    cudaStreamWaitEvent(s2, evRoot, 0);

    transpose_h<<<dim3(DFF_ / 32, DIM_ / 32), dim3(32, 8), 0, s2>>>(w1, w1h, DIM_, DFF_);
    transpose_h<<<dim3(DIM_ / 32, DFF_ / 32), dim3(32, 8), 0, s2>>>(w2, w2h, DFF_, DIM_);
    cudaEventRecord(evT, s2);

    // main: conv scan (stats fused into phase1) -> LN2
    phazor_prep<<<1, DIM_>>>(phazor, phinit);
    conv_phase1<<<B_ * NC, DIM_>>>(x, ln_g, ln_b);
    conv_phase2<<<dim3(B_, DIM_ / 256), 256>>>();
    conv_phase3<<<B_ * NC, DIM_>>>(x, ln_g, ln_b, lre, lim, y);
    ln2_kernel<<<NTOK / 8, 256>>>(y, ln_g, ln_b, h2h);

    // join: GEMMs need the transposed weights
    cudaStreamWaitEvent(0, evT, 0);

    dim3 g1(DFF_ / CTN, NTOK / 128);   // 32 x 64
    hgemm<0><<<g1, 256, GEMM_SMEM>>>(h2h, w1h, b1, nullptr, act, nullptr, NTOK, DFF_, DIM_);
    dim3 g2(DIM_ / CTN, NTOK / 128);   // 8 x 64
    hgemm<1><<<g2, 256, GEMM_SMEM>>>(act, w2h, b2, y, nullptr, out, NTOK, DIM_, DFF_);
}

// round 10
// speedup vs baseline: 1.9008x; 1.0056x over previous
#include <cuda_runtime.h>
#include <cuda_fp16.h>
#include <math.h>
#include <stdint.h>

// Problem constants
#define B_   4
#define L_   2048
#define DIM_ 1024
#define DFF_ 4096
#define NTOK (B_ * L_)            // 8192 rows
#define CS   32                    // conv chunk size
#define NC   (L_ / CS)             // 64 chunks

// -------- scratch (static __device__ — no allocations allowed) --------
__device__ float   g_y  [(size_t)NTOK * DIM_];
__device__ __half  g_h2h[(size_t)NTOK * DIM_];   // LN2 out, fp16
__device__ __half  g_act[(size_t)NTOK * DFF_];   // SiLU out, fp16
__device__ __half  g_w1h[(size_t)DFF_ * DIM_];   // w1^T fp16 [N=4096,K=1024]
__device__ __half  g_w2h[(size_t)DIM_ * DFF_];   // w2^T fp16 [N=1024,K=4096]
__device__ float2  g_stat[NTOK];                 // LN1 (mu, rstd) per row
__device__ float2  g_carry[B_ * NC * DIM_];
__device__ float2  g_zin  [B_ * NC * DIM_];
__device__ float2  g_p    [DIM_];
__device__ float2  g_pinit[DIM_];
__device__ float2  g_p32  [DIM_];

// ================= helpers =================
__device__ __forceinline__ uint32_t smem_u32(const void* p) {
    return (uint32_t)__cvta_generic_to_shared(p);
}
__device__ __forceinline__ void cp_async16(uint32_t saddr, const void* gptr) {
    asm volatile("cp.async.cg.shared.global [%0], [%1], 16;" :: "r"(saddr), "l"(gptr));
}
#define CP_COMMIT()  asm volatile("cp.async.commit_group;" ::: "memory")
#define CP_WAIT(n)   asm volatile("cp.async.wait_group %0;" :: "n"(n) : "memory")
#define LDSM_X4(r0, r1, r2, r3, addr) \
    asm volatile("ldmatrix.sync.aligned.m8n8.x4.shared.b16 {%0,%1,%2,%3}, [%4];" \
                 : "=r"(r0), "=r"(r1), "=r"(r2), "=r"(r3) : "r"(addr))

// ================= phazor precompute =================
__global__ void phazor_prep(const float* __restrict__ phazor,
                            const float* __restrict__ phazor_init) {
    int d = blockIdx.x * blockDim.x + threadIdx.x;
    if (d >= DIM_) return;
    float pr = phazor[2 * d], pim = phazor[2 * d + 1];
    float pa = sqrtf(pr * pr + pim * pim);
    float s = expf(-pa) / pa;
    float2 p = make_float2(pr * s, pim * s);
    g_p[d] = p;
    g_pinit[d] = make_float2(phazor_init[2 * d], phazor_init[2 * d + 1]);
    float2 q = p;                              // p^32 via 5 squarings
    #pragma unroll
    for (int i = 0; i < 5; i++) {
        float nr = q.x * q.x - q.y * q.y;
        q.y = 2.f * q.x * q.y;
        q.x = nr;
    }
    g_p32[d] = q;
}

// ========== conv phase1 (fused LN1 stats + scan carry) ==========
// Block (b,c): 32 rows x 1024 dims, 1024 threads.
// Pass A: warp j computes stats of row j (8 float4 per lane).
// Pass B: thread d scans its column (x re-read from hot L2).
__global__ void conv_phase1(const float* __restrict__ x, const float* __restrict__ lng,
                            const float* __restrict__ lnb) {
    __shared__ float2 sh_stat[CS];
    int b = blockIdx.x >> 6, c = blockIdx.x & 63;
    int tid = threadIdx.x;
    int row0 = b * L_ + c * CS;

    // ---- pass A: stats (warp per row) ----
    {
        int j = tid >> 5, lane = tid & 31;
        const float4* xr = (const float4*)(x + (size_t)(row0 + j) * DIM_);
        float s = 0.f, ss = 0.f;
        #pragma unroll
        for (int i = 0; i < 8; i++) {
            float4 v = xr[lane + 32 * i];
            s  += v.x + v.y + v.z + v.w;
            ss += v.x * v.x + v.y * v.y + v.z * v.z + v.w * v.w;
        }
        #pragma unroll
        for (int o = 16; o > 0; o >>= 1) {
            s  += __shfl_xor_sync(0xffffffffu, s, o);
            ss += __shfl_xor_sync(0xffffffffu, ss, o);
        }
        if (lane == 0) {
            float mu = s * (1.f / DIM_);
            float var = ss * (1.f / DIM_) - mu * mu;
            float2 st = make_float2(mu, rsqrtf(var + 1e-5f));
            sh_stat[j] = st;
            g_stat[row0 + j] = st;   // for conv_phase3
        }
    }
    __syncthreads();

    // ---- pass B: scan ----
    int d = tid;
    float2 p = g_p[d];
    float gd = lng[d], bd = lnb[d];
    float zr = 0.f, zi = 0.f;
    const float* xp = x + (size_t)row0 * DIM_ + d;
    #pragma unroll 8
    for (int j = 0; j < CS; j++) {
        float2 st = sh_stat[j];
        float hv = (xp[(size_t)j * DIM_] - st.x) * st.y * gd + bd;
        float nr = p.x * zr - p.y * zi + hv;
        zi = p.x * zi + p.y * zr;
        zr = nr;
    }
    g_carry[(b * NC + c) * DIM_ + d] = make_float2(zr, zi);
}

// ========== conv phase2: exclusive prefix across 64 chunks ==========
__global__ void conv_phase2() {
    int b = blockIdx.x;
    int d = blockIdx.y * 256 + threadIdx.x;
    float2 pc = g_p32[d];
    float zr = 0.f, zi = 0.f;
    #pragma unroll
    for (int half = 0; half < 2; half++) {
        float2 cv[32];
        #pragma unroll
        for (int i = 0; i < 32; i++)
            cv[i] = g_carry[(b * NC + half * 32 + i) * DIM_ + d];
        #pragma unroll
        for (int i = 0; i < 32; i++) {
            g_zin[(b * NC + half * 32 + i) * DIM_ + d] = make_float2(zr, zi);
            float nr = pc.x * zr - pc.y * zi + cv[i].x;
            zi = pc.x * zi + pc.y * zr + cv[i].y;
            zr = nr;
        }
    }
}

// ========== conv phase3 (scan -> y) + fused LN2 (y -> h2h fp16) ==========
__global__ void conv_phase3(const float* __restrict__ x, const float* __restrict__ lng,
                            const float* __restrict__ lnb,
                            const float* __restrict__ lre, const float* __restrict__ lim,
                            float* __restrict__ y, __half* __restrict__ h2h) {
    __shared__ float2 sh2[CS];
    int b = blockIdx.x >> 6, c = blockIdx.x & 63;
    int tid = threadIdx.x;
    int row0 = b * L_ + c * CS;

    // ---- pass A: scan, emit y = conv + past + x ----
    {
        int d = tid;
        float2 p  = g_p[d];
        float2 pi = g_pinit[d];
        float2 pc = g_p32[d];
        float2 z  = g_zin[(b * NC + c) * DIM_ + d];
        float gd = lng[d], bd = lnb[d];
        float twr = 1.f, twi = 0.f;
        for (int i = 0; i < c; i++) {
            float nr = twr * pc.x - twi * pc.y;
            twi = twr * pc.y + twi * pc.x;
            twr = nr;
        }
        float pwr = twr * p.x - twi * p.y;
        float pwi = twr * p.y + twi * p.x;
        float lr = lre[b * DIM_ + d], li = lim[b * DIM_ + d];
        size_t base = (size_t)row0 * DIM_ + d;
        #pragma unroll 8
        for (int j = 0; j < CS; j++) {
            float xv = x[base + (size_t)j * DIM_];
            float2 st = g_stat[row0 + j];
            float hv = (xv - st.x) * st.y * gd + bd;
            float nr = p.x * z.x - p.y * z.y + hv;
            z.y = p.x * z.y + p.y * z.x;
            z.x = nr;
            float val = pi.x * z.x - pi.y * z.y + lr * pwr - li * pwi;
            y[base + (size_t)j * DIM_] = val + xv;
            float npr = pwr * p.x - pwi * p.y;
            pwi = pwr * p.y + pwi * p.x;
            pwr = npr;
        }
    }
    __syncthreads();   // y writes visible block-wide

    // ---- pass B: LN2 stats (warp per row, y from hot L2) ----
    int j = tid >> 5, lane = tid & 31;
    const float4* yr = (const float4*)(y + (size_t)(row0 + j) * DIM_);
    {
        float s = 0.f, ss = 0.f;
        #pragma unroll
        for (int i = 0; i < 8; i++) {
            float4 v = yr[lane + 32 * i];
            s  += v.x + v.y + v.z + v.w;
            ss += v.x * v.x + v.y * v.y + v.z * v.z + v.w * v.w;
        }
        #pragma unroll
        for (int o = 16; o > 0; o >>= 1) {
            s  += __shfl_xor_sync(0xffffffffu, s, o);
            ss += __shfl_xor_sync(0xffffffffu, ss, o);
        }
        if (lane == 0) {
            float mu = s * (1.f / DIM_);
            float var = ss * (1.f / DIM_) - mu * mu;
            sh2[j] = make_float2(mu, rsqrtf(var + 1e-5f));
        }
    }
    __syncthreads();

    // ---- pass C: apply LN2, emit h2h fp16 ----
    {
        float2 st = sh2[j];
        float mu = st.x, inv = st.y;
        #pragma unroll
        for (int i = 0; i < 8; i++) {
            float4 v  = yr[lane + 32 * i];
            float4 gv = ((const float4*)lng)[lane + 32 * i];
            float4 bv = ((const float4*)lnb)[lane + 32 * i];
            __half2 h0 = __floats2half2_rn((v.x - mu) * inv * gv.x + bv.x,
                                           (v.y - mu) * inv * gv.y + bv.y);
            __half2 h1 = __floats2half2_rn((v.z - mu) * inv * gv.z + bv.z,
                                           (v.w - mu) * inv * gv.w + bv.w);
            uint2 pk = make_uint2(*(uint32_t*)&h0, *(uint32_t*)&h1);
            *(uint2*)(h2h + (size_t)(row0 + j) * DIM_ + (lane + 32 * i) * 4) = pk;
        }
    }
}

// ======== weight transpose + cast ([K,N] fp32 -> [N,K] fp16) ========
__global__ void transpose_h(const float* __restrict__ in, __half* __restrict__ out,
                            int R, int Ccols) {
    __shared__ float t[32][33];
    int bx = blockIdx.x * 32, by = blockIdx.y * 32;
    int tx = threadIdx.x, ty = threadIdx.y;
    #pragma unroll
    for (int j = 0; j < 32; j += 8)
        t[ty + j][tx] = in[(size_t)(by + ty + j) * Ccols + bx + tx];
    __syncthreads();
    #pragma unroll
    for (int j = 0; j < 32; j += 8)
        out[(size_t)(bx + ty + j) * R + by + tx] = __float2half(t[tx][ty + j]);
}

// ======= fp16 tensor-core GEMM (mma.sync m16n8k16 + ldmatrix) =======
// CTA tile 128x128, 2 CTAs/SM, BK=32, 8 warps (2x4), warp tile 64x32,
// 3-stage cp.async ring, 1 barrier per k-tile.
// EPI==0: act(half) = silu(acc + bias);  EPI==1: out(f32) = acc + bias + res
#define TBK 32
#define ROW_H 72                         // padded stride in halves (144B)
#define CTN 128
#define GEMM_SMEM (3 * (128 + CTN) * ROW_H * 2)   // 110592

template <int EPI>
__global__ __launch_bounds__(256, 2) void hgemm(
    const __half* __restrict__ A, const __half* __restrict__ Bt,
    const float* __restrict__ bias, const float* __restrict__ res,
    __half* __restrict__ Ch, float* __restrict__ Cf, int M, int N, int K) {
    constexpr int WNW = CTN / 4;         // 32
    constexpr int NT  = WNW / 8;         // 4
    constexpr int NP  = NT / 2;          // 2
    constexpr int BCH = CTN / 64;        // 2
    constexpr int A_H = 128 * ROW_H;
    constexpr int STG = (128 + CTN) * ROW_H;

    extern __shared__ __half sm[];
    int tid = threadIdx.x, wid = tid >> 5, lane = tid & 31;
    int g = lane >> 2, l4 = lane & 3;
    int wm = (wid & 1) * 64;
    int wn = (wid >> 1) * WNW;
    int bm = blockIdx.y * 128, bn = blockIdx.x * CTN;
    const int NK = K / TBK;

    int mat = lane >> 3, rr = lane & 7;
    uint32_t aoff[4], boff[NP];
    #pragma unroll
    for (int mt = 0; mt < 4; mt++)
        aoff[mt] = (uint32_t)((wm + mt * 16 + (mat & 1) * 8 + rr) * 144 + (mat >> 1) * 16);
    #pragma unroll
    for (int np = 0; np < NP; np++)
        boff[np] = (uint32_t)((wn + np * 16 + (mat >> 1) * 8 + rr) * 144 + (mat & 1) * 16);

    auto load_stage = [&](int s, int k0) {
        uint32_t base = smem_u32(sm + (size_t)s * STG);
        #pragma unroll
        for (int i = 0; i < 2; i++) {
            int c = tid + i * 256;
            int row = c >> 2, kc = c & 3;
            cp_async16(base + row * 144 + kc * 16,
                       A + (size_t)(bm + row) * K + k0 + kc * 8);
        }
        uint32_t bb = base + A_H * 2;
        #pragma unroll
        for (int i = 0; i < BCH; i++) {
            int c = tid + i * 256;
            int row = c >> 2, kc = c & 3;
            cp_async16(bb + row * 144 + kc * 16,
                       Bt + (size_t)(bn + row) * K + k0 + kc * 8);
        }
    };

    float acc[4][NT][4];
    #pragma unroll
    for (int i = 0; i < 4; i++)
        #pragma unroll
        for (int j = 0; j < NT; j++)
            #pragma unroll
            for (int r = 0; r < 4; r++) acc[i][j][r] = 0.f;

    load_stage(0, 0);       CP_COMMIT();
    load_stage(1, TBK);     CP_COMMIT();

    for (int kt = 0; kt < NK; kt++) {
        if (kt + 1 < NK) CP_WAIT(1); else CP_WAIT(0);
        __syncthreads();
        if (kt + 2 < NK) load_stage((kt + 2) % 3, (kt + 2) * TBK);
        CP_COMMIT();
        uint32_t sa = smem_u32(sm + (size_t)(kt % 3) * STG);
        uint32_t sb = sa + A_H * 2;
        #pragma unroll
        for (int ks = 0; ks < TBK; ks += 16) {
            uint32_t af[4][4], bf[NT][2];
            #pragma unroll
            for (int mt = 0; mt < 4; mt++)
                LDSM_X4(af[mt][0], af[mt][1], af[mt][2], af[mt][3],
                        sa + aoff[mt] + ks * 2);
            #pragma unroll
            for (int np = 0; np < NP; np++)
                LDSM_X4(bf[2 * np][0], bf[2 * np][1], bf[2 * np + 1][0], bf[2 * np + 1][1],
                        sb + boff[np] + ks * 2);
            #pragma unroll
            for (int mt = 0; mt < 4; mt++)
                #pragma unroll
                for (int nt = 0; nt < NT; nt++) {
                    asm volatile(
                        "mma.sync.aligned.m16n8k16.row.col.f32.f16.f16.f32 "
                        "{%0,%1,%2,%3}, {%4,%5,%6,%7}, {%8,%9}, {%0,%1,%2,%3};"
                        : "+f"(acc[mt][nt][0]), "+f"(acc[mt][nt][1]),
                          "+f"(acc[mt][nt][2]), "+f"(acc[mt][nt][3])
                        : "r"(af[mt][0]), "r"(af[mt][1]), "r"(af[mt][2]), "r"(af[mt][3]),
                          "r"(bf[nt][0]), "r"(bf[nt][1]));
                }
        }
    }

    // ---- epilogue ----
    #pragma unroll
    for (int mt = 0; mt < 4; mt++) {
        int r0 = bm + wm + mt * 16 + g;
        #pragma unroll
        for (int nt = 0; nt < NT; nt++) {
            int col = bn + wn + nt * 8 + 2 * l4;
            float bv0 = bias[col], bv1 = bias[col + 1];
            #pragma unroll
            for (int h = 0; h < 2; h++) {
                int row = r0 + h * 8;
                size_t off = (size_t)row * N + col;
                float v0 = acc[mt][nt][2 * h + 0] + bv0;
                float v1 = acc[mt][nt][2 * h + 1] + bv1;
                if (EPI == 0) {
                    v0 = v0 / (1.f + __expf(-v0));
                    v1 = v1 / (1.f + __expf(-v1));
                    __half2 hv = __floats2half2_rn(v0, v1);
                    *(__half2*)&Ch[off] = hv;
                } else {
                    v0 += res[off];
                    v1 += res[off + 1];
                    *(float2*)&Cf[off] = make_float2(v0, v1);
                }
            }
        }
    }
}

// ================= launch =================
extern "C" void kernel_launch(void* const* d_in, const int* in_sizes, int n_in,
                              void* d_out, int out_size) {
    const float* x      = (const float*)d_in[0];
    const float* ln_g   = (const float*)d_in[1];
    const float* ln_b   = (const float*)d_in[2];
    const float* phazor = (const float*)d_in[3];
    const float* phinit = (const float*)d_in[4];
    const float* w1     = (const float*)d_in[5];
    const float* b1     = (const float*)d_in[6];
    const float* w2     = (const float*)d_in[7];
    const float* b2     = (const float*)d_in[8];
    const float* lre    = (const float*)d_in[9];
    const float* lim    = (const float*)d_in[10];
    float* out = (float*)d_out;

    float *y;
    __half *h2h, *act, *w1h, *w2h;
    cudaGetSymbolAddress((void**)&y,   g_y);
    cudaGetSymbolAddress((void**)&h2h, g_h2h);
    cudaGetSymbolAddress((void**)&act, g_act);
    cudaGetSymbolAddress((void**)&w1h, g_w1h);
    cudaGetSymbolAddress((void**)&w2h, g_w2h);

    cudaFuncSetAttribute(hgemm<0>, cudaFuncAttributeMaxDynamicSharedMemorySize, GEMM_SMEM);
    cudaFuncSetAttribute(hgemm<1>, cudaFuncAttributeMaxDynamicSharedMemorySize, GEMM_SMEM);

    // fork a second stream for the weight transposes; they overlap the
    // conv chain and join before GEMM1. (Objects persist — bounded leak;
    // destroying capture-referenced objects would be illegal.)
    cudaStream_t s2;
    cudaStreamCreateWithFlags(&s2, cudaStreamNonBlocking);
    cudaEvent_t evRoot, evT;
    cudaEventCreateWithFlags(&evRoot, cudaEventDisableTiming);
    cudaEventCreateWithFlags(&evT,    cudaEventDisableTiming);

    cudaEventRecord(evRoot, 0);
    cudaStreamWaitEvent(s2, evRoot, 0);

    transpose_h<<<dim3(DFF_ / 32, DIM_ / 32), dim3(32, 8), 0, s2>>>(w1, w1h, DIM_, DFF_);
    transpose_h<<<dim3(DIM_ / 32, DFF_ / 32), dim3(32, 8), 0, s2>>>(w2, w2h, DFF_, DIM_);
    cudaEventRecord(evT, s2);

    // main: conv scan (LN1 stats fused into phase1, LN2 fused into phase3)
    phazor_prep<<<1, DIM_>>>(phazor, phinit);
    conv_phase1<<<B_ * NC, DIM_>>>(x, ln_g, ln_b);
    conv_phase2<<<dim3(B_, DIM_ / 256), 256>>>();
    conv_phase3<<<B_ * NC, DIM_>>>(x, ln_g, ln_b, lre, lim, y, h2h);

    // join: GEMMs need the transposed weights
    cudaStreamWaitEvent(0, evT, 0);

    dim3 g1(DFF_ / CTN, NTOK / 128);   // 32 x 64
    hgemm<0><<<g1, 256, GEMM_SMEM>>>(h2h, w1h, b1, nullptr, act, nullptr, NTOK, DFF_, DIM_);
    dim3 g2(DIM_ / CTN, NTOK / 128);   // 8 x 64
    hgemm<1><<<g2, 256, GEMM_SMEM>>>(act, w2h, b2, y, nullptr, out, NTOK, DIM_, DFF_);
}